// round 14
// baseline (speedup 1.0000x reference)
#include <cuda_runtime.h>
#include <math.h>
#include <float.h>
#include <stdint.h>

#define S_ASP 4
#define C_CL  1024
#define NKEYS 131072
#define DK    128
#define DA    2048
#define M_TOP 32
#define K_MAX 64
#define BB    64
#define NPC   128
#define M_CAND 4096
#define EPSF  1e-8f
#define DN    128            /* keys per MMA block == NPC */

__device__ float g_part[32 * S_ASP * DK * BB];
__device__ float g_qwT [S_ASP * DK * BB];       /* [s][k][b] */
__device__ float g_qbk [S_ASP * BB * DK];       /* [s][b][k] */
__device__ float g_cscore[BB * C_CL];
__device__ int   g_topc [BB * M_TOP];
__device__ float g_sif  [(size_t)BB * NKEYS];   /* 32 MB; holds exps after k_smax_part */
__device__ float g_refS [BB * M_CAND];          /* exact fp32 candidate scores */
__device__ unsigned long long g_clmask[C_CL];
__device__ int   g_rank [C_CL * BB];
__device__ float g_cmax [BB * 32];
__device__ float g_csum [BB * 32];
__device__ float g_rmax [BB];
__device__ float g_rsum [BB];

/* ---- warp mma tf32 m16n8k8 ---- */
__device__ __forceinline__ void mma_tf32(float* c, const unsigned* a, const unsigned* b) {
    asm volatile("mma.sync.aligned.m16n8k8.row.col.f32.tf32.tf32.f32 "
                 "{%0,%1,%2,%3}, {%4,%5,%6,%7}, {%8,%9}, {%0,%1,%2,%3};"
                 : "+f"(c[0]), "+f"(c[1]), "+f"(c[2]), "+f"(c[3])
                 : "r"(a[0]), "r"(a[1]), "r"(a[2]), "r"(a[3]), "r"(b[0]), "r"(b[1]));
}
__device__ __forceinline__ unsigned smem_u32(const void* p) {
    return (unsigned)__cvta_generic_to_shared(p);
}
__device__ __forceinline__ void cpa16(unsigned d, const void* s) {
    asm volatile("cp.async.ca.shared.global [%0], [%1], 16;" :: "r"(d), "l"(s));
}
__device__ __forceinline__ void cpa_commit() { asm volatile("cp.async.commit_group;"); }
__device__ __forceinline__ void cpa_wait0()  { asm volatile("cp.async.wait_group 0;"); }

/* FMA-pipe exp: exp(y) for y in [-87, 0]; rel err ~1e-8. No MUFU. */
__device__ __forceinline__ float fast_exp(float y) {
    float t = y * 1.4426950408889634f;
    int e = __float2int_rn(t);
    float f = t - (float)e;
    float p = 1.54035304e-4f;
    p = fmaf(p, f, 1.33335581e-3f);
    p = fmaf(p, f, 9.61812911e-3f);
    p = fmaf(p, f, 5.55041087e-2f);
    p = fmaf(p, f, 2.40226507e-1f);
    p = fmaf(p, f, 6.93147181e-1f);
    p = fmaf(p, f, 1.0f);
    return __int_as_float(__float_as_int(p) + (e << 23));
}

/* K1: query GEMM partials. grid 256 = s(4) x ac(32) x kh(2), 128 thr */
__global__ void __launch_bounds__(128) k_qpart(const float* __restrict__ WQ,
                                               const float* __restrict__ z) {
    int bx = blockIdx.x, s = bx >> 6, ac = (bx >> 1) & 31, kh = bx & 1;
    int a0 = ac * 64;
    __shared__ float sW[64 * 65], sZ[64 * 65];
    int tid = threadIdx.x;
    for (int idx = tid; idx < 64 * 64; idx += 128) {
        int kl = idx >> 6, aa = idx & 63;
        sW[kl * 65 + aa] = WQ[(size_t)s * DK * DA + (kh * 64 + kl) * DA + a0 + aa];
    }
    for (int idx = tid; idx < 64 * 64; idx += 128) {
        int b = idx >> 6, aa = idx & 63;
        sZ[b * 65 + aa] = z[b * DA + a0 + aa];
    }
    __syncthreads();
    int krow = tid >> 3, bcol = tid & 7;
    float acc[4][8];
#pragma unroll
    for (int i = 0; i < 4; i++)
#pragma unroll
        for (int j = 0; j < 8; j++) acc[i][j] = 0.f;
    for (int aa = 0; aa < 64; aa++) {
        float qk[4], zb[8];
#pragma unroll
        for (int i = 0; i < 4; i++) qk[i] = sW[(krow * 4 + i) * 65 + aa];
#pragma unroll
        for (int j = 0; j < 8; j++) zb[j] = sZ[(bcol * 8 + j) * 65 + aa];
#pragma unroll
        for (int i = 0; i < 4; i++)
#pragma unroll
            for (int j = 0; j < 8; j++) acc[i][j] = fmaf(qk[i], zb[j], acc[i][j]);
    }
#pragma unroll
    for (int i = 0; i < 4; i++)
#pragma unroll
        for (int j = 0; j < 8; j++)
            g_part[((ac * S_ASP + s) * DK + kh * 64 + krow * 4 + i) * BB + bcol * 8 + j] = acc[i][j];
}

/* K2: combine + l2norm + aspect softmax weight */
__global__ void __launch_bounds__(128) k_qcombine(const float* __restrict__ aw) {
    int s = blockIdx.x >> 6, b = blockIdx.x & 63, k = threadIdx.x;
    float q = 0.f;
    for (int ac = 0; ac < 32; ac++) q += g_part[((ac * S_ASP + s) * DK + k) * BB + b];
    __shared__ float red[DK];
    red[k] = q * q; __syncthreads();
    for (int off = 64; off > 0; off >>= 1) {
        if (k < off) red[k] += red[k + off];
        __syncthreads();
    }
    float rinv = 1.f / (sqrtf(red[0]) + EPSF);
    float a0 = aw[0], a1 = aw[1], a2 = aw[2], a3 = aw[3];
    float mx = fmaxf(fmaxf(a0, a1), fmaxf(a2, a3));
    float e0 = expf(a0 - mx), e1 = expf(a1 - mx), e2 = expf(a2 - mx), e3 = expf(a3 - mx);
    float ws = (s == 0 ? e0 : s == 1 ? e1 : s == 2 ? e2 : e3) / (e0 + e1 + e2 + e3);
    float v = ws * q * rinv;
    g_qwT[(s * DK + k) * BB + b] = v;
    g_qbk[(s * BB + b) * DK + k] = v;
}

/* K3: centroid scores, smem-cached. grid 64 (16 centroids each), 512 thr. */
__global__ void __launch_bounds__(512) k_centroid(const float* __restrict__ cent) {
    extern __shared__ float cs[];
    float* sqw = cs;            /* [s*128+k][b] */
    float* scn = cs + 32768;    /* [ci][s*128+k] */
    float* srn = cs + 40960;    /* [ci*4+s] */
    int tid = threadIdx.x;
    int c0 = blockIdx.x * 16;

    {
        const float4* src = (const float4*)g_qwT;
        float4* dst = (float4*)sqw;
#pragma unroll
        for (int i = 0; i < 16; i++) dst[tid + 512 * i] = src[tid + 512 * i];
    }
    {
#pragma unroll
        for (int ii = 0; ii < 4; ii++) {
            int i = tid + 512 * ii;
            int ci = i >> 7;
            int r = i & 127;
            int s = r >> 5, k4 = (r & 31) << 2;
            ((float4*)scn)[i] = *(const float4*)(cent + ((size_t)s * C_CL + c0 + ci) * DK + k4);
        }
    }
    __syncthreads();
    if (tid < 64) {
        int ci = tid >> 2, s = tid & 3;
        const float* row = scn + ci * 512 + s * DK;
        float ss = 0.f;
#pragma unroll
        for (int k = 0; k < DK; k += 4) {
            float4 v = *(const float4*)(row + k);
            ss += v.x * v.x + v.y * v.y + v.z * v.z + v.w * v.w;
        }
        srn[tid] = 1.f / (sqrtf(ss) + EPSF);
    }
    __syncthreads();
#pragma unroll
    for (int it = 0; it < 2; it++) {
        int i = tid + 512 * it;
        int ci = i >> 6, b = i & 63;
        float acc = 0.f;
#pragma unroll
        for (int s = 0; s < S_ASP; s++) {
            const float* qw = sqw + s * DK * BB + b;
            const float* cr = scn + ci * 512 + s * DK;
            float p = 0.f;
#pragma unroll 8
            for (int k = 0; k < DK; k++) p = fmaf(qw[k * BB], cr[k], p);
            acc = fmaf(p, srn[ci * 4 + s], acc);
        }
        g_cscore[b * C_CL + c0 + ci] = acc;
    }
}

/* K4: top-32 of 1024 via bitonic sort; also zeroes this block's clmask slice. */
__global__ void __launch_bounds__(512) k_topc() {
    int b = blockIdx.x, tid = threadIdx.x;
    __shared__ unsigned long long key[C_CL];
    if (tid < 16) g_clmask[b * 16 + tid] = 0ull;
#pragma unroll
    for (int r = 0; r < 2; r++) {
        int i = tid + 512 * r;
        float v = g_cscore[b * C_CL + i];
        unsigned int u = __float_as_uint(v);
        u ^= (u & 0x80000000u) ? 0xFFFFFFFFu : 0x80000000u;
        unsigned int su = ~u;
        key[i] = ((unsigned long long)su << 32) | (unsigned int)i;
    }
    __syncthreads();
    for (int size = 2; size <= C_CL; size <<= 1) {
        for (int stride = size >> 1; stride > 0; stride >>= 1) {
            int i = ((tid & ~(stride - 1)) << 1) | (tid & (stride - 1));
            int j = i + stride;
            bool up = ((i & size) == 0);
            unsigned long long a = key[i], c = key[j];
            bool sw = up ? (a > c) : (a < c);
            if (sw) { key[i] = c; key[j] = a; }
            __syncthreads();
        }
    }
    if (tid < M_TOP) g_topc[b * M_TOP + tid] = (int)(key[tid] & 0xFFFFFFFFu);
}

__global__ void __launch_bounds__(32) k_clmask() {
    int b = blockIdx.x, r = threadIdx.x;
    int c = g_topc[b * M_TOP + r];
    atomicOr(&g_clmask[c], 1ull << b);
    g_rank[c * BB + b] = r;
}

/* K5: fused tf32 warp-mma dense pass + exact fp32 candidate scores.
   grid 1024 (block == cluster), 256 thr. smem 224.8 KB -> 1 CTA/SM. */
__global__ void __launch_bounds__(256, 1) k_mma(const float* __restrict__ keys) {
    extern __shared__ float sm[];
    float* skb[2] = {sm, sm + 16384};
    float* sqb[2] = {sm + 32768, sm + 40960};
    float* srn  = sm + 49152;
    float* eacc = sm + 49280;
    int*   bl   = (int*)(sm + 49280 + 8192);

    int tid = threadIdx.x, wid = tid >> 5, lane = tid & 31;
    int wm = wid & 3, wn = wid >> 2;
    int g = lane >> 2, j = lane & 3;
    int n0 = blockIdx.x * DN;

    unsigned long long mask = g_clmask[blockIdx.x];
    int nb = __popcll(mask);
    if (tid == 0) {
        unsigned long long m = mask;
        for (int i = 0; i < nb; i++) {
            bl[i] = __ffsll((long long)m) - 1;
            m &= m - 1;
        }
    }
    for (int i = tid; i < nb * DN; i += 256) eacc[i] = 0.f;

    float acc[2][4][4];
#pragma unroll
    for (int mt = 0; mt < 2; mt++)
#pragma unroll
        for (int nt = 0; nt < 4; nt++)
#pragma unroll
            for (int c = 0; c < 4; c++) acc[mt][nt][c] = 0.f;

    {
        const float* kb = keys + (size_t)n0 * DK;
        unsigned kd = smem_u32(skb[0]);
#pragma unroll
        for (int i = 0; i < 16; i++) {
            int idx = tid + 256 * i;
            int row = idx >> 5, kc = (idx & 31) << 2;
            cpa16(kd + (row * DK + (kc ^ (4 * (row & 7)))) * 4, kb + (size_t)row * DK + kc);
        }
        unsigned qd = smem_u32(sqb[0]);
#pragma unroll
        for (int i = 0; i < 8; i++) {
            int idx = tid + 256 * i;
            int n = idx >> 5, kc = (idx & 31) << 2;
            cpa16(qd + (n * DK + (kc ^ (4 * (n & 7)))) * 4, g_qbk + (size_t)n * DK + kc);
        }
        cpa_commit();
        cpa_wait0();
    }
    __syncthreads();

    for (int s = 0; s < S_ASP; s++) {
        int cur = s & 1;
        float* sk = skb[cur];
        float* sq = sqb[cur];
        if (s < S_ASP - 1) {
            const float* kb = keys + ((size_t)(s + 1) * NKEYS + n0) * DK;
            unsigned kd = smem_u32(skb[cur ^ 1]);
#pragma unroll
            for (int i = 0; i < 16; i++) {
                int idx = tid + 256 * i;
                int row = idx >> 5, kc = (idx & 31) << 2;
                cpa16(kd + (row * DK + (kc ^ (4 * (row & 7)))) * 4, kb + (size_t)row * DK + kc);
            }
            const float* qb = g_qbk + (size_t)(s + 1) * BB * DK;
            unsigned qd = smem_u32(sqb[cur ^ 1]);
#pragma unroll
            for (int i = 0; i < 8; i++) {
                int idx = tid + 256 * i;
                int n = idx >> 5, kc = (idx & 31) << 2;
                cpa16(qd + (n * DK + (kc ^ (4 * (n & 7)))) * 4, qb + (size_t)n * DK + kc);
            }
            cpa_commit();
        }
        {
            int row = tid >> 1, half = tid & 1;
            int sw = 4 * (row & 7);
            float ss = 0.f;
#pragma unroll
            for (int i = 0; i < 16; i++) {
                int kf = half * 64 + i * 4;
                float4 v = *(const float4*)(sk + row * DK + (kf ^ sw));
                ss += v.x * v.x + v.y * v.y + v.z * v.z + v.w * v.w;
            }
            ss += __shfl_xor_sync(0xffffffffu, ss, 1);
            if (half == 0) srn[row] = 1.f / (sqrtf(ss) + EPSF);
        }
        __syncthreads();

        float rn0[2], rn1[2];
#pragma unroll
        for (int mt = 0; mt < 2; mt++) {
            rn0[mt] = srn[wm * 32 + mt * 16 + g];
            rn1[mt] = srn[wm * 32 + mt * 16 + 8 + g];
        }
#pragma unroll
        for (int kt = 0; kt < 16; kt++) {
            int k0 = kt * 8;
            unsigned bf[4][2];
#pragma unroll
            for (int nt = 0; nt < 4; nt++) {
                int n = wn * 32 + nt * 8 + g;
                int sw = 4 * (n & 7);
                bf[nt][0] = __float_as_uint(sq[n * DK + ((k0 + j) ^ sw)]);
                bf[nt][1] = __float_as_uint(sq[n * DK + ((k0 + 4 + j) ^ sw)]);
            }
            unsigned af[2][4];
#pragma unroll
            for (int mt = 0; mt < 2; mt++) {
                int r = wm * 32 + mt * 16 + g;
                int sw = 4 * (r & 7);
                af[mt][0] = __float_as_uint(sk[r * DK + ((k0 + j) ^ sw)] * rn0[mt]);
                af[mt][1] = __float_as_uint(sk[(r + 8) * DK + ((k0 + j) ^ sw)] * rn1[mt]);
                af[mt][2] = __float_as_uint(sk[r * DK + ((k0 + 4 + j) ^ sw)] * rn0[mt]);
                af[mt][3] = __float_as_uint(sk[(r + 8) * DK + ((k0 + 4 + j) ^ sw)] * rn1[mt]);
            }
#pragma unroll
            for (int mt = 0; mt < 2; mt++)
#pragma unroll
                for (int nt = 0; nt < 4; nt++)
                    mma_tf32(acc[mt][nt], af[mt], bf[nt]);
        }
        for (int p = tid; p < nb * DN; p += 256) {
            int slot = p >> 7, keyr = p & 127;
            int b = bl[slot];
            int swk = 4 * (keyr & 7), swq = 4 * (b & 7);
            const float* kr = sk + keyr * DK;
            const float* qr = sq + b * DK;
            float d = 0.f;
#pragma unroll 8
            for (int k = 0; k < DK; k++)
                d = fmaf(kr[k ^ swk], qr[k ^ swq], d);
            eacc[p] = fmaf(d, srn[keyr], eacc[p]);
        }
        if (s < S_ASP - 1) cpa_wait0();
        __syncthreads();
    }

    for (int p = tid; p < nb * DN; p += 256) {
        int slot = p >> 7, keyr = p & 127;
        int b = bl[slot];
        int rank = g_rank[blockIdx.x * BB + b];
        g_refS[b * M_CAND + rank * DN + keyr] = eacc[p];
    }

    /* epilogue: stage accs to smem (132-pad rows), then coalesced float4 writes */
    float* so = skb[0];
#pragma unroll
    for (int mt = 0; mt < 2; mt++) {
        int kl0 = wm * 32 + mt * 16 + g;
#pragma unroll
        for (int nt = 0; nt < 4; nt++) {
            int b = wn * 32 + nt * 8 + 2 * j;
            so[b * 132 + kl0]             = acc[mt][nt][0];
            so[(b + 1) * 132 + kl0]       = acc[mt][nt][1];
            so[b * 132 + kl0 + 8]         = acc[mt][nt][2];
            so[(b + 1) * 132 + kl0 + 8]   = acc[mt][nt][3];
        }
    }
    __syncthreads();
#pragma unroll
    for (int i = 0; i < 8; i++) {
        int idx = tid + 256 * i;
        int b = idx >> 5, q4 = (idx & 31) << 2;
        float4 v = *(const float4*)(so + b * 132 + q4);
        *(float4*)(g_sif + (size_t)b * NKEYS + n0 + q4) = v;
    }
}

/* K6: per-chunk softmax stats + STORE exp values back to g_sif.
   grid 2048 = b*32+c, 256 thr. exp via FMA-pipe poly (no MUFU). */
__global__ void __launch_bounds__(256) k_smax_part() {
    int b = blockIdx.x >> 5, c = blockIdx.x & 31, tid = threadIdx.x;
    float4* row = (float4*)(g_sif + (size_t)b * NKEYS + c * 4096);
    float4 v[4];
    float m = -FLT_MAX;
#pragma unroll
    for (int i = 0; i < 4; i++) {
        v[i] = row[tid + 256 * i];
        m = fmaxf(m, fmaxf(fmaxf(v[i].x, v[i].y), fmaxf(v[i].z, v[i].w)));
    }
    __shared__ float smem[256];
    smem[tid] = m; __syncthreads();
    for (int off = 128; off > 0; off >>= 1) {
        if (tid < off) smem[tid] = fmaxf(smem[tid], smem[tid + off]);
        __syncthreads();
    }
    float bm = smem[0]; __syncthreads();
    float sum = 0.f;
#pragma unroll
    for (int i = 0; i < 4; i++) {
        v[i].x = fast_exp(v[i].x - bm);
        v[i].y = fast_exp(v[i].y - bm);
        v[i].z = fast_exp(v[i].z - bm);
        v[i].w = fast_exp(v[i].w - bm);
        sum += v[i].x + v[i].y + v[i].z + v[i].w;
        row[tid + 256 * i] = v[i];          /* store exp(v - chunk_max) */
    }
    smem[tid] = sum; __syncthreads();
    for (int off = 128; off > 0; off >>= 1) {
        if (tid < off) smem[tid] += smem[tid + off];
        __syncthreads();
    }
    if (tid == 0) { g_cmax[b * 32 + c] = bm; g_csum[b * 32 + c] = smem[0]; }
}

/* K7: combine chunk stats. grid 64, 32 thr */
__global__ void __launch_bounds__(32) k_smax_comb() {
    int b = blockIdx.x, t = threadIdx.x;
    float m = g_cmax[b * 32 + t], s = g_csum[b * 32 + t];
    float M = m;
    for (int off = 16; off > 0; off >>= 1) M = fmaxf(M, __shfl_xor_sync(0xffffffffu, M, off));
    float part = s * __expf(m - M);
    for (int off = 16; off > 0; off >>= 1) part += __shfl_xor_sync(0xffffffffu, part, off);
    if (t == 0) { g_rmax[b] = M; g_rsum[b] = part; }
}

/* K8: write soft_full = stored_exp * exp(cm - M)/rsum. Pure scale, no bulk exp. */
__global__ void __launch_bounds__(256) k_smax_write(float* __restrict__ out) {
    int b = blockIdx.x >> 5, c = blockIdx.x & 31, tid = threadIdx.x;
    const float4* row = (const float4*)(g_sif + (size_t)b * NKEYS + c * 4096);
    float4* orow = (float4*)(out + 2 * BB * K_MAX + (size_t)b * NKEYS + c * 4096);
    float scale = __expf(g_cmax[b * 32 + c] - g_rmax[b]) / g_rsum[b];
#pragma unroll
    for (int i = 0; i < 4; i++) {
        float4 v = row[tid + 256 * i];
        orow[tid + 256 * i] = make_float4(v.x * scale, v.y * scale, v.z * scale, v.w * scale);
    }
}

/* K9: refine + top-64 + alphas. grid 64, 256 thr. Reads exact scores. */
__global__ void __launch_bounds__(256) k_refine(const float* __restrict__ taup,
                                                const float* __restrict__ lamp,
                                                const int* __restrict__ warmp,
                                                float* __restrict__ out) {
    int b = blockIdx.x, tid = threadIdx.x;
    int wid = tid >> 5, lane = tid & 31;
    __shared__ float raw[M_CAND];
    __shared__ float bvw[256];
    __shared__ float wv[8]; __shared__ int wi[8];
    __shared__ int win_i;
    __shared__ float vals[K_MAX];
    __shared__ int   gids[K_MAX];
    __shared__ float sD;
    float tau = taup[0], lam = lamp[0];
    int warm = warmp[0];

    float lsum = 0.f;
    for (int r = 0; r < 16; r++) {
        int i = tid + 256 * r;
        float si = g_refS[b * M_CAND + i];
        float v;
        if (warm) v = si;
        else {
            float g = 1.f / (1.f + expf(-lam * (si - tau)));
            v = g * expf(si);
        }
        raw[i] = v;
        lsum += v;
    }
    bvw[tid] = lsum; __syncthreads();
    for (int off = 128; off > 0; off >>= 1) {
        if (tid < off) bvw[tid] += bvw[tid + off];
        __syncthreads();
    }
    if (tid == 0) sD = bvw[0] + EPSF;
    __syncthreads();
    if (!warm) {
        float invD = 1.f / sD;
        for (int r = 0; r < 16; r++) raw[tid + 256 * r] *= invD;
    }
    __syncthreads();

    float lv = -FLT_MAX; int li = tid;
    for (int r = 0; r < 16; r++) {
        int i = tid + 256 * r;
        float v = raw[i];
        if (v > lv) { lv = v; li = i; }
    }
    for (int rr = 0; rr < K_MAX; rr++) {
        float bv = lv; int bidx = li;
#pragma unroll
        for (int off = 16; off > 0; off >>= 1) {
            float ov = __shfl_xor_sync(0xffffffffu, bv, off);
            int   oi = __shfl_xor_sync(0xffffffffu, bidx, off);
            if (ov > bv || (ov == bv && oi < bidx)) { bv = ov; bidx = oi; }
        }
        if (lane == 0) { wv[wid] = bv; wi[wid] = bidx; }
        __syncthreads();
        if (tid == 0) {
            float gbv = wv[0]; int gbi = wi[0];
            for (int w = 1; w < 8; w++) {
                if (wv[w] > gbv || (wv[w] == gbv && wi[w] < gbi)) { gbv = wv[w]; gbi = wi[w]; }
            }
            win_i = gbi;
            vals[rr] = gbv;
            gids[rr] = g_topc[b * M_TOP + (gbi >> 7)] * NPC + (gbi & 127);
        }
        __syncthreads();
        if ((win_i & 255) == tid) {
            raw[win_i] = -FLT_MAX;
            lv = -FLT_MAX; li = tid;
            for (int r = 0; r < 16; r++) {
                int i = tid + 256 * r;
                float v = raw[i];
                if (v > lv) { lv = v; li = i; }
            }
        }
        __syncthreads();
    }

    if (tid == 0) {
        float alphas[K_MAX];
        if (warm) {
            float m = -FLT_MAX;
            for (int r = 0; r < K_MAX; r++) m = fmaxf(m, vals[r]);
            float ssum = 0.f;
            for (int r = 0; r < K_MAX; r++) { alphas[r] = expf(vals[r] - m); ssum += alphas[r]; }
            float inv = 1.f / ssum;
            for (int r = 0; r < K_MAX; r++) alphas[r] *= inv;
        } else {
            float ssum = 0.f;
            for (int r = 0; r < K_MAX; r++) ssum += vals[r];
            float inv = 1.f / (ssum + EPSF);
            for (int r = 0; r < K_MAX; r++) alphas[r] = vals[r] * inv;
        }
        for (int r = 0; r < K_MAX; r++) {
            out[b * K_MAX + r] = alphas[r];
            out[BB * K_MAX + b * K_MAX + r] = (float)gids[r];
        }
    }
}

extern "C" void kernel_launch(void* const* d_in, const int* in_sizes, int n_in,
                              void* d_out, int out_size) {
    const float* z    = (const float*)d_in[0];
    const float* keys = (const float*)d_in[1];
    const float* WQ   = (const float*)d_in[2];
    const float* aw   = (const float*)d_in[3];
    const float* tau  = (const float*)d_in[4];
    const float* cent = (const float*)d_in[5];
    const float* lam  = (const float*)d_in[6];
    const int*   warm = (const int*)d_in[7];
    float* out = (float*)d_out;

    const size_t mma_smem  = (size_t)(49280 + 8192 + 64) * sizeof(float);  /* 224.8 KB */
    const size_t cent_smem = (size_t)(32768 + 8192 + 64) * sizeof(float);  /* 160.25 KB */
    cudaFuncSetAttribute(k_mma, cudaFuncAttributeMaxDynamicSharedMemorySize, (int)mma_smem);
    cudaFuncSetAttribute(k_centroid, cudaFuncAttributeMaxDynamicSharedMemorySize, (int)cent_smem);

    k_qpart<<<256, 128>>>(WQ, z);
    k_qcombine<<<256, 128>>>(aw);
    k_centroid<<<64, 512, cent_smem>>>(cent);
    k_topc<<<64, 512>>>();
    k_clmask<<<64, 32>>>();
    k_mma<<<NKEYS / DN, 256, mma_smem>>>(keys);
    k_smax_part<<<2048, 256>>>();
    k_smax_comb<<<64, 32>>>();
    k_smax_write<<<2048, 256>>>(out);
    k_refine<<<64, 256>>>(tau, lam, warm, out);
}